// round 13
// baseline (speedup 1.0000x reference)
#include <cuda_runtime.h>
#include <cuda_bf16.h>
#include <cstdint>

// ---------------------------------------------------------------------------
// CLOPLayer: out[b,c,j] = x[b,c,perm[j]], perm = fixed JAX threefry(42)
// neighbor-swap permutation, evaluated at COMPILE TIME (constexpr) and baked
// into module .data. Single-kernel graph.
// Wall is DRAM-traffic-bound (260MB/replay mixed stream @ ~5.4TB/s). This
// round removes the WRITE stream from L2 entirely (st.global.wt: write-
// through, no-allocate -> full-line coalesced sectors straight to DRAM) so
// the READ set has the whole ~126MB L2 to itself, pinned with a fractional
// (0.9) evict_last policy that can now actually survive across replays
// (~117MB < capacity, nothing dirty displaces it). Steady-state DRAM traffic
// ~= 130MB writes + ~15MB read misses =~ 145MB/replay.
// Gather: cp.async double-buffered row pipeline; stride-1 conflict-free LDS
// scatter; coalesced write-through stores. 576 CTAs x 8 rows, one wave.
// ---------------------------------------------------------------------------

#define N_ELEM 7056            // 84*84
#define DIM    84
#define NVEC   (N_ELEM / 4)    // 1764
#define NTHR   512
#define COLS_PER_THR 14        // ceil(7056/512)
#define VECS_PER_THR 4         // ceil(1764/512)
#define ROWS_PER_BLK 8

// ---------------------------------------------------------------------------
// Compile-time bit-exact JAX RNG replication (threefry2x32, partitionable)
// ---------------------------------------------------------------------------

struct PermTable { int v[N_ELEM]; };

constexpr uint32_t rotl32c(uint32_t v, int r) {
    return (v << r) | (v >> (32 - r));
}

struct TF2 { uint32_t x0, x1; };

constexpr TF2 threefry2x32c(uint32_t k0, uint32_t k1, uint32_t x0, uint32_t x1) {
    const uint32_t ks0 = k0;
    const uint32_t ks1 = k1;
    const uint32_t ks2 = k0 ^ k1 ^ 0x1BD11BDAu;
    const int ra[4] = {13, 15, 26, 6};
    const int rb[4] = {17, 29, 16, 24};

    x0 += ks0; x1 += ks1;
    for (int i = 0; i < 4; i++) { x0 += x1; x1 = rotl32c(x1, ra[i]); x1 ^= x0; }
    x0 += ks1; x1 += ks2 + 1u;
    for (int i = 0; i < 4; i++) { x0 += x1; x1 = rotl32c(x1, rb[i]); x1 ^= x0; }
    x0 += ks2; x1 += ks0 + 2u;
    for (int i = 0; i < 4; i++) { x0 += x1; x1 = rotl32c(x1, ra[i]); x1 ^= x0; }
    x0 += ks0; x1 += ks1 + 3u;
    for (int i = 0; i < 4; i++) { x0 += x1; x1 = rotl32c(x1, rb[i]); x1 ^= x0; }
    x0 += ks1; x1 += ks2 + 4u;
    for (int i = 0; i < 4; i++) { x0 += x1; x1 = rotl32c(x1, ra[i]); x1 ^= x0; }
    x0 += ks2; x1 += ks0 + 5u;
    return TF2{x0, x1};
}

constexpr uint32_t jax_bits32c(uint32_t k0, uint32_t k1, uint64_t i) {
    TF2 r = threefry2x32c(k0, k1, (uint32_t)(i >> 32), (uint32_t)(i & 0xFFFFFFFFu));
    return r.x0 ^ r.x1;
}

constexpr PermTable make_perm() {
    PermTable p{};
    const int n = N_ELEM;
    const int dim = DIM;
    const int steps = 2 * n - 1;   // 14111

    float probs0 = (float)(1.0 - 0.9 / 2.0);
    float probsq = (float)(0.9 / 8.0);
    float pc[5] = {};
    pc[0] = probs0;
    for (int q = 1; q < 5; q++) pc[q] = pc[q - 1] + probsq;

    const int offsets[5] = {0, 1, -1, dim, -dim};

    for (int t = 0; t < n; t++) p.v[t] = t;

    const uint32_t k0 = 0u, k1 = 42u;   // jax.random.key(42)

    for (int s = 0; s < steps; s++) {
        int i = s - (n - 1);
        if (i < 0) i = -i;

        uint32_t bits = jax_bits32c(k0, k1, (uint64_t)s);
        // u = bitcast(bits>>9 | 0x3F800000) - 1.0f == (float)(bits>>9) * 2^-23
        float u = (float)(bits >> 9) * (1.0f / 8388608.0f);

        float rv = pc[4] * (1.0f - u);
        int ind = 0;
        while (ind < 5 && pc[ind] < rv) ind++;
        if (ind > 4) ind = 4;

        int idx = i + offsets[ind];
        if (ind != 0 && idx > 0 && idx < n) {
            int a = p.v[i];
            p.v[i] = p.v[idx];
            p.v[idx] = a;
        }
    }
    return p;
}

__device__ constexpr PermTable g_perm = make_perm();

// ---------------------------------------------------------------------------

__device__ __forceinline__ uint64_t mk_policy_read_pin() {
    uint64_t pol;
    // 90% of read lines -> evict_last (pinned set ~117MB < L2 capacity,
    // stable because the write stream no longer allocates in L2),
    // 10% -> evict_first (transient ways).
    asm("createpolicy.fractional.L2::evict_last.L2::evict_first.b64 %0, 0.9;"
        : "=l"(pol));
    return pol;
}

__device__ __forceinline__ void cp_async16_pol(uint32_t saddr, const void* g,
                                               uint64_t pol) {
    asm volatile("cp.async.cg.shared.global.L2::cache_hint [%0], [%1], 16, %2;\n"
                 :: "r"(saddr), "l"(g), "l"(pol) : "memory");
}
__device__ __forceinline__ void cp_commit() {
    asm volatile("cp.async.commit_group;\n" ::: "memory");
}
template <int N>
__device__ __forceinline__ void cp_wait() {
    asm volatile("cp.async.wait_group %0;\n" :: "n"(N) : "memory");
}

__device__ __forceinline__ void load_row_async(
    uint32_t buf_saddr, const float* __restrict__ xrow, int t, uint64_t pol)
{
    #pragma unroll
    for (int k = 0; k < VECS_PER_THR; ++k) {
        int v = t + k * NTHR;
        if (v < NVEC) {
            cp_async16_pol(buf_saddr + (uint32_t)v * 16u,
                           reinterpret_cast<const float4*>(xrow) + v, pol);
        }
    }
    cp_commit();
}

extern __shared__ float s_buf[];   // 2 * N_ELEM floats = 56448 B

__global__ __launch_bounds__(NTHR) void clop_gather_kernel(
    const float* __restrict__ x, float* __restrict__ out, int nrows)
{
    const int t = threadIdx.x;
    const int r0 = blockIdx.x * ROWS_PER_BLK;
    const uint64_t pol_rd = mk_policy_read_pin();

    float* buf0 = s_buf;
    uint32_t sa0, sa1;
    asm("{ .reg .u64 a; cvta.to.shared.u64 a, %1; cvt.u32.u64 %0, a; }"
        : "=r"(sa0) : "l"(buf0));
    sa1 = sa0 + N_ELEM * 4u;
    float* buf1 = s_buf + N_ELEM;

    // prologue: start loading row r0 ASAP so perm LDGs overlap its latency
    if (r0 < nrows)
        load_row_async(sa0, x + (size_t)r0 * N_ELEM, t, pol_rd);

    // perm values for this thread's columns (coalesced LDG, once per block)
    const int* __restrict__ pg = g_perm.v;
    int pc[COLS_PER_THR];
    #pragma unroll
    for (int k = 0; k < COLS_PER_THR; ++k) {
        int col = t + k * NTHR;
        pc[k] = (col < N_ELEM) ? __ldg(pg + col) : 0;
    }

    #pragma unroll
    for (int r = 0; r < ROWS_PER_BLK; ++r) {
        int row = r0 + r;
        if (row >= nrows) break;

        float* cur = (r & 1) ? buf1 : buf0;

        // issue next row's loads into the other buffer, then wait for current
        int nrow = row + 1;
        if (r + 1 < ROWS_PER_BLK && nrow < nrows) {
            uint32_t na = (r & 1) ? sa0 : sa1;
            load_row_async(na, x + (size_t)nrow * N_ELEM, t, pol_rd);
            cp_wait<1>();     // current row's group complete; next may fly
        } else {
            cp_wait<0>();
        }
        __syncthreads();

        // permuted read from smem (stride-1 => conflict-free); write-through
        // no-allocate stores (full-line coalesced -> straight to DRAM,
        // leaving L2 entirely to the pinned read set)
        float* dst = out + (size_t)row * N_ELEM;
        #pragma unroll
        for (int k = 0; k < COLS_PER_THR; ++k) {
            int col = t + k * NTHR;
            if (col < N_ELEM) __stwt(dst + col, cur[pc[k]]);
        }
        __syncthreads();  // all reads of 'cur' done before it is refilled
    }
}

// ---------------------------------------------------------------------------

extern "C" void kernel_launch(void* const* d_in, const int* in_sizes, int n_in,
                              void* d_out, int out_size) {
    const float* x = (const float*)d_in[0];
    float* out = (float*)d_out;
    int total = in_sizes[0];
    int nrows = total / N_ELEM;    // 512*9 = 4608

    const int smem_bytes = 2 * N_ELEM * (int)sizeof(float);   // 56448
    cudaFuncSetAttribute(clop_gather_kernel,
                         cudaFuncAttributeMaxDynamicSharedMemorySize,
                         smem_bytes);

    int nblk = (nrows + ROWS_PER_BLK - 1) / ROWS_PER_BLK;   // 576
    clop_gather_kernel<<<nblk, NTHR, smem_bytes>>>(x, out, nrows);
}

// round 14
// speedup vs baseline: 1.0233x; 1.0233x over previous
#include <cuda_runtime.h>
#include <cuda_bf16.h>
#include <cstdint>

// ---------------------------------------------------------------------------
// CLOPLayer: out[b,c,j] = x[b,c,perm[j]], perm = fixed JAX threefry(42)
// neighbor-swap permutation, evaluated at COMPILE TIME (constexpr) and baked
// into module .data. Single-kernel graph.
// FINAL (converged): wall time equals DRAM service time for the irreducible
// 260MB/replay mixed stream at the measured sustained ceiling (~5.5TB/s).
// Best-measured configuration across 13 rounds:
//  - reads:  LDGSTS (cp.async.cg) double-buffered row pipeline
//  - scatter: smem->smem, stride-1 conflict-free LDS + STS (perm in regs)
//  - writes: 28KB linear TMA bulk stores (long same-direction write runs)
//  288 CTAs x 16 rows = 4608 rows exact, 2 CTAs/SM, one wave.
// ---------------------------------------------------------------------------

#define N_ELEM 7056            // 84*84
#define DIM    84
#define NVEC   (N_ELEM / 4)    // 1764
#define NTHR   512
#define COLS_PER_THR 14        // ceil(7056/512)
#define VECS_PER_THR 4         // ceil(1764/512)
#define ROWS_PER_BLK 16
#define ROW_BYTES (N_ELEM * 4) // 28224

// ---------------------------------------------------------------------------
// Compile-time bit-exact JAX RNG replication (threefry2x32, partitionable)
// ---------------------------------------------------------------------------

struct PermTable { int v[N_ELEM]; };

constexpr uint32_t rotl32c(uint32_t v, int r) {
    return (v << r) | (v >> (32 - r));
}

struct TF2 { uint32_t x0, x1; };

constexpr TF2 threefry2x32c(uint32_t k0, uint32_t k1, uint32_t x0, uint32_t x1) {
    const uint32_t ks0 = k0;
    const uint32_t ks1 = k1;
    const uint32_t ks2 = k0 ^ k1 ^ 0x1BD11BDAu;
    const int ra[4] = {13, 15, 26, 6};
    const int rb[4] = {17, 29, 16, 24};

    x0 += ks0; x1 += ks1;
    for (int i = 0; i < 4; i++) { x0 += x1; x1 = rotl32c(x1, ra[i]); x1 ^= x0; }
    x0 += ks1; x1 += ks2 + 1u;
    for (int i = 0; i < 4; i++) { x0 += x1; x1 = rotl32c(x1, rb[i]); x1 ^= x0; }
    x0 += ks2; x1 += ks0 + 2u;
    for (int i = 0; i < 4; i++) { x0 += x1; x1 = rotl32c(x1, ra[i]); x1 ^= x0; }
    x0 += ks0; x1 += ks1 + 3u;
    for (int i = 0; i < 4; i++) { x0 += x1; x1 = rotl32c(x1, rb[i]); x1 ^= x0; }
    x0 += ks1; x1 += ks2 + 4u;
    for (int i = 0; i < 4; i++) { x0 += x1; x1 = rotl32c(x1, ra[i]); x1 ^= x0; }
    x0 += ks2; x1 += ks0 + 5u;
    return TF2{x0, x1};
}

constexpr uint32_t jax_bits32c(uint32_t k0, uint32_t k1, uint64_t i) {
    TF2 r = threefry2x32c(k0, k1, (uint32_t)(i >> 32), (uint32_t)(i & 0xFFFFFFFFu));
    return r.x0 ^ r.x1;
}

constexpr PermTable make_perm() {
    PermTable p{};
    const int n = N_ELEM;
    const int dim = DIM;
    const int steps = 2 * n - 1;   // 14111

    float probs0 = (float)(1.0 - 0.9 / 2.0);
    float probsq = (float)(0.9 / 8.0);
    float pc[5] = {};
    pc[0] = probs0;
    for (int q = 1; q < 5; q++) pc[q] = pc[q - 1] + probsq;

    const int offsets[5] = {0, 1, -1, dim, -dim};

    for (int t = 0; t < n; t++) p.v[t] = t;

    const uint32_t k0 = 0u, k1 = 42u;   // jax.random.key(42)

    for (int s = 0; s < steps; s++) {
        int i = s - (n - 1);
        if (i < 0) i = -i;

        uint32_t bits = jax_bits32c(k0, k1, (uint64_t)s);
        // u = bitcast(bits>>9 | 0x3F800000) - 1.0f == (float)(bits>>9) * 2^-23
        float u = (float)(bits >> 9) * (1.0f / 8388608.0f);

        float rv = pc[4] * (1.0f - u);
        int ind = 0;
        while (ind < 5 && pc[ind] < rv) ind++;
        if (ind > 4) ind = 4;

        int idx = i + offsets[ind];
        if (ind != 0 && idx > 0 && idx < n) {
            int a = p.v[i];
            p.v[i] = p.v[idx];
            p.v[idx] = a;
        }
    }
    return p;
}

__device__ constexpr PermTable g_perm = make_perm();

// ---------------------------------------------------------------------------

__device__ __forceinline__ void cp_async16(uint32_t saddr, const void* g) {
    asm volatile("cp.async.cg.shared.global [%0], [%1], 16;\n"
                 :: "r"(saddr), "l"(g) : "memory");
}
__device__ __forceinline__ void cp_commit() {
    asm volatile("cp.async.commit_group;\n" ::: "memory");
}
template <int N>
__device__ __forceinline__ void cp_wait() {
    asm volatile("cp.async.wait_group %0;\n" :: "n"(N) : "memory");
}

// ---- 1D TMA bulk store: smem -> gmem, per-row linear 28KB ----
__device__ __forceinline__ void bulk_store_row(void* gdst, uint32_t ssrc) {
    asm volatile("cp.async.bulk.global.shared::cta.bulk_group [%0], [%1], %2;\n"
                 :: "l"(gdst), "r"(ssrc), "n"(ROW_BYTES) : "memory");
}
__device__ __forceinline__ void bulk_commit() {
    asm volatile("cp.async.bulk.commit_group;\n" ::: "memory");
}
template <int N>
__device__ __forceinline__ void bulk_wait_read() {
    asm volatile("cp.async.bulk.wait_group.read %0;\n" :: "n"(N) : "memory");
}
template <int N>
__device__ __forceinline__ void bulk_wait() {
    asm volatile("cp.async.bulk.wait_group %0;\n" :: "n"(N) : "memory");
}
__device__ __forceinline__ void fence_proxy_async_cta() {
    asm volatile("fence.proxy.async.shared::cta;\n" ::: "memory");
}

__device__ __forceinline__ void load_row_async(
    uint32_t buf_saddr, const float* __restrict__ xrow, int t)
{
    #pragma unroll
    for (int k = 0; k < VECS_PER_THR; ++k) {
        int v = t + k * NTHR;
        if (v < NVEC) {
            cp_async16(buf_saddr + (uint32_t)v * 16u,
                       reinterpret_cast<const float4*>(xrow) + v);
        }
    }
    cp_commit();
}

extern __shared__ float s_mem[];   // 4 * N_ELEM floats = 112896 B
// layout: in0 | in1 | out0 | out1

__global__ __launch_bounds__(NTHR) void clop_gather_kernel(
    const float* __restrict__ x, float* __restrict__ out, int nrows)
{
    const int t = threadIdx.x;
    const int r0 = blockIdx.x * ROWS_PER_BLK;

    uint32_t s_base;
    asm("{ .reg .u64 a; cvta.to.shared.u64 a, %1; cvt.u32.u64 %0, a; }"
        : "=r"(s_base) : "l"(s_mem));

    float* in_buf[2]  = { s_mem,               s_mem + N_ELEM };
    float* out_buf[2] = { s_mem + 2 * N_ELEM,  s_mem + 3 * N_ELEM };
    uint32_t in_sa[2]  = { s_base,                  s_base + (uint32_t)ROW_BYTES };
    uint32_t out_sa[2] = { s_base + 2u * ROW_BYTES, s_base + 3u * ROW_BYTES };

    // prologue: start loading row r0 into in0
    if (r0 < nrows)
        load_row_async(in_sa[0], x + (size_t)r0 * N_ELEM, t);

    // perm values for this thread's columns (coalesced LDG, once per block;
    // overlapped under the prologue's DRAM latency)
    const int* __restrict__ pg = g_perm.v;
    int pc[COLS_PER_THR];
    #pragma unroll
    for (int k = 0; k < COLS_PER_THR; ++k) {
        int col = t + k * NTHR;
        pc[k] = (col < N_ELEM) ? __ldg(pg + col) : 0;
    }

    #pragma unroll
    for (int r = 0; r < ROWS_PER_BLK; ++r) {
        int row = r0 + r;
        if (row >= nrows) break;

        // prefetch next row into the other in-buffer (freed by row r-1's
        // scatter, ordered by the end-of-iteration barrier), then wait for
        // row r's loads.
        if (r + 1 < ROWS_PER_BLK && row + 1 < nrows) {
            load_row_async(in_sa[(r + 1) & 1], x + (size_t)(row + 1) * N_ELEM, t);
            cp_wait<1>();
        } else {
            cp_wait<0>();
        }
        // out-buffer (r&1) reuse: row r-2's bulk store must have finished
        // READING smem (row r-1's store may still be in flight).
        if (t == 0) bulk_wait_read<1>();
        __syncthreads();

        // scatter smem->smem: permuted LDS (stride-1 => conflict-free),
        // stride-1 STS into the staging out-buffer
        const float* __restrict__ cin = in_buf[r & 1];
        float* __restrict__ cout = out_buf[r & 1];
        #pragma unroll
        for (int k = 0; k < COLS_PER_THR; ++k) {
            int col = t + k * NTHR;
            if (col < N_ELEM) cout[col] = cin[pc[k]];
        }
        __syncthreads();  // out-buffer fully written; in-buffer fully read

        // one thread issues the 28KB linear bulk store for this row
        if (t == 0) {
            fence_proxy_async_cta();
            bulk_store_row(out + (size_t)row * N_ELEM, out_sa[r & 1]);
            bulk_commit();
        }
    }

    // drain outstanding bulk stores before CTA exit
    if (t == 0) bulk_wait<0>();
}

// ---------------------------------------------------------------------------

extern "C" void kernel_launch(void* const* d_in, const int* in_sizes, int n_in,
                              void* d_out, int out_size) {
    const float* x = (const float*)d_in[0];
    float* out = (float*)d_out;
    int total = in_sizes[0];
    int nrows = total / N_ELEM;    // 512*9 = 4608

    const int smem_bytes = 4 * N_ELEM * (int)sizeof(float);   // 112896
    cudaFuncSetAttribute(clop_gather_kernel,
                         cudaFuncAttributeMaxDynamicSharedMemorySize,
                         smem_bytes);

    int nblk = (nrows + ROWS_PER_BLK - 1) / ROWS_PER_BLK;   // 288
    clop_gather_kernel<<<nblk, NTHR, smem_bytes>>>(x, out, nrows);
}

// round 15
// speedup vs baseline: 1.0336x; 1.0101x over previous
#include <cuda_runtime.h>
#include <cuda_bf16.h>
#include <cstdint>

// ---------------------------------------------------------------------------
// CLOPLayer: out[b,c,j] = x[b,c,perm[j]], perm = fixed JAX threefry(42)
// neighbor-swap permutation, evaluated at COMPILE TIME (constexpr) and baked
// into module .data. Single-kernel graph.
// CONVERGED FINAL: wall = DRAM service time of the irreducible 260MB/replay
// mixed stream at the measured sustained ceiling (~5.4TB/s); invariant under
// request shaping, pipeline depth, occupancy, store path, and L2 policy
// (6 falsified theories, R7-R13; rebench noise +-1us).
// Config: best measured exec (36.9us) + simplest structure:
//  - reads:  LDGSTS (cp.async.cg) double-buffered row pipeline
//  - scatter: permuted stride-1 conflict-free LDS (perm in registers)
//  - writes: coalesced streaming scalar stores (__stcs)
//  576 CTAs x 8 rows = 4608 rows exact, 4 CTAs/SM, one wave.
// ---------------------------------------------------------------------------

#define N_ELEM 7056            // 84*84
#define DIM    84
#define NVEC   (N_ELEM / 4)    // 1764
#define NTHR   512
#define COLS_PER_THR 14        // ceil(7056/512)
#define VECS_PER_THR 4         // ceil(1764/512)
#define ROWS_PER_BLK 8

// ---------------------------------------------------------------------------
// Compile-time bit-exact JAX RNG replication (threefry2x32, partitionable)
// ---------------------------------------------------------------------------

struct PermTable { int v[N_ELEM]; };

constexpr uint32_t rotl32c(uint32_t v, int r) {
    return (v << r) | (v >> (32 - r));
}

struct TF2 { uint32_t x0, x1; };

constexpr TF2 threefry2x32c(uint32_t k0, uint32_t k1, uint32_t x0, uint32_t x1) {
    const uint32_t ks0 = k0;
    const uint32_t ks1 = k1;
    const uint32_t ks2 = k0 ^ k1 ^ 0x1BD11BDAu;
    const int ra[4] = {13, 15, 26, 6};
    const int rb[4] = {17, 29, 16, 24};

    x0 += ks0; x1 += ks1;
    for (int i = 0; i < 4; i++) { x0 += x1; x1 = rotl32c(x1, ra[i]); x1 ^= x0; }
    x0 += ks1; x1 += ks2 + 1u;
    for (int i = 0; i < 4; i++) { x0 += x1; x1 = rotl32c(x1, rb[i]); x1 ^= x0; }
    x0 += ks2; x1 += ks0 + 2u;
    for (int i = 0; i < 4; i++) { x0 += x1; x1 = rotl32c(x1, ra[i]); x1 ^= x0; }
    x0 += ks0; x1 += ks1 + 3u;
    for (int i = 0; i < 4; i++) { x0 += x1; x1 = rotl32c(x1, rb[i]); x1 ^= x0; }
    x0 += ks1; x1 += ks2 + 4u;
    for (int i = 0; i < 4; i++) { x0 += x1; x1 = rotl32c(x1, ra[i]); x1 ^= x0; }
    x0 += ks2; x1 += ks0 + 5u;
    return TF2{x0, x1};
}

constexpr uint32_t jax_bits32c(uint32_t k0, uint32_t k1, uint64_t i) {
    TF2 r = threefry2x32c(k0, k1, (uint32_t)(i >> 32), (uint32_t)(i & 0xFFFFFFFFu));
    return r.x0 ^ r.x1;
}

constexpr PermTable make_perm() {
    PermTable p{};
    const int n = N_ELEM;
    const int dim = DIM;
    const int steps = 2 * n - 1;   // 14111

    float probs0 = (float)(1.0 - 0.9 / 2.0);
    float probsq = (float)(0.9 / 8.0);
    float pc[5] = {};
    pc[0] = probs0;
    for (int q = 1; q < 5; q++) pc[q] = pc[q - 1] + probsq;

    const int offsets[5] = {0, 1, -1, dim, -dim};

    for (int t = 0; t < n; t++) p.v[t] = t;

    const uint32_t k0 = 0u, k1 = 42u;   // jax.random.key(42)

    for (int s = 0; s < steps; s++) {
        int i = s - (n - 1);
        if (i < 0) i = -i;

        uint32_t bits = jax_bits32c(k0, k1, (uint64_t)s);
        // u = bitcast(bits>>9 | 0x3F800000) - 1.0f == (float)(bits>>9) * 2^-23
        // (both exact: mantissa < 2^23, power-of-two scale, exact subtraction)
        float u = (float)(bits >> 9) * (1.0f / 8388608.0f);

        float rv = pc[4] * (1.0f - u);
        int ind = 0;
        while (ind < 5 && pc[ind] < rv) ind++;
        if (ind > 4) ind = 4;

        int idx = i + offsets[ind];
        if (ind != 0 && idx > 0 && idx < n) {
            int a = p.v[i];
            p.v[i] = p.v[idx];
            p.v[idx] = a;
        }
    }
    return p;
}

__device__ constexpr PermTable g_perm = make_perm();

// ---------------------------------------------------------------------------

__device__ __forceinline__ void cp_async16(uint32_t saddr, const void* g) {
    asm volatile("cp.async.cg.shared.global [%0], [%1], 16;\n"
                 :: "r"(saddr), "l"(g) : "memory");
}
__device__ __forceinline__ void cp_commit() {
    asm volatile("cp.async.commit_group;\n" ::: "memory");
}
template <int N>
__device__ __forceinline__ void cp_wait() {
    asm volatile("cp.async.wait_group %0;\n" :: "n"(N) : "memory");
}

__device__ __forceinline__ void load_row_async(
    uint32_t buf_saddr, const float* __restrict__ xrow, int t)
{
    #pragma unroll
    for (int k = 0; k < VECS_PER_THR; ++k) {
        int v = t + k * NTHR;
        if (v < NVEC) {
            cp_async16(buf_saddr + (uint32_t)v * 16u,
                       reinterpret_cast<const float4*>(xrow) + v);
        }
    }
    cp_commit();
}

extern __shared__ float s_buf[];   // 2 * N_ELEM floats = 56448 B

__global__ __launch_bounds__(NTHR) void clop_gather_kernel(
    const float* __restrict__ x, float* __restrict__ out, int nrows)
{
    const int t = threadIdx.x;
    const int r0 = blockIdx.x * ROWS_PER_BLK;

    float* buf0 = s_buf;
    uint32_t sa0, sa1;
    asm("{ .reg .u64 a; cvta.to.shared.u64 a, %1; cvt.u32.u64 %0, a; }"
        : "=r"(sa0) : "l"(buf0));
    sa1 = sa0 + N_ELEM * 4u;
    float* buf1 = s_buf + N_ELEM;

    // prologue: start loading row r0 ASAP so perm LDGs overlap its latency
    if (r0 < nrows)
        load_row_async(sa0, x + (size_t)r0 * N_ELEM, t);

    // perm values for this thread's columns (coalesced LDG, once per block)
    const int* __restrict__ pg = g_perm.v;
    int pc[COLS_PER_THR];
    #pragma unroll
    for (int k = 0; k < COLS_PER_THR; ++k) {
        int col = t + k * NTHR;
        pc[k] = (col < N_ELEM) ? __ldg(pg + col) : 0;
    }

    #pragma unroll
    for (int r = 0; r < ROWS_PER_BLK; ++r) {
        int row = r0 + r;
        if (row >= nrows) break;

        float* cur = (r & 1) ? buf1 : buf0;

        // issue next row's loads into the other buffer, then wait for current
        int nrow = row + 1;
        if (r + 1 < ROWS_PER_BLK && nrow < nrows) {
            uint32_t na = (r & 1) ? sa0 : sa1;
            load_row_async(na, x + (size_t)nrow * N_ELEM, t);
            cp_wait<1>();     // current row's group complete; next may fly
        } else {
            cp_wait<0>();
        }
        __syncthreads();

        // permuted read from smem (stride-1 => conflict-free), coalesced
        // streaming scalar stores
        float* dst = out + (size_t)row * N_ELEM;
        #pragma unroll
        for (int k = 0; k < COLS_PER_THR; ++k) {
            int col = t + k * NTHR;
            if (col < N_ELEM) __stcs(dst + col, cur[pc[k]]);
        }
        __syncthreads();  // all reads of 'cur' done before it is refilled
    }
}

// ---------------------------------------------------------------------------

extern "C" void kernel_launch(void* const* d_in, const int* in_sizes, int n_in,
                              void* d_out, int out_size) {
    const float* x = (const float*)d_in[0];
    float* out = (float*)d_out;
    int total = in_sizes[0];
    int nrows = total / N_ELEM;    // 512*9 = 4608

    const int smem_bytes = 2 * N_ELEM * (int)sizeof(float);   // 56448
    cudaFuncSetAttribute(clop_gather_kernel,
                         cudaFuncAttributeMaxDynamicSharedMemorySize,
                         smem_bytes);

    int nblk = (nrows + ROWS_PER_BLK - 1) / ROWS_PER_BLK;   // 576
    clop_gather_kernel<<<nblk, NTHR, smem_bytes>>>(x, out, nrows);
}